// round 8
// baseline (speedup 1.0000x reference)
#include <cuda_runtime.h>
#include <cstdint>
#include <math.h>

#define MTOK 4096
#define HDIM 2048
#define NEXP 8
#define MOEI 1408
#define SHI  5632
#define CAP  4096

#define BM 128
#define BN 128
#define BK 32
#define NSTAGE 3
#define STAGE_FLOATS (2 * 128 * 32)              // A tile + B tile, no padding (swizzled)
#define STAGE_BYTES  (STAGE_FLOATS * 4)          // 32768
#define SMEM_TOTAL   (NSTAGE * STAGE_BYTES)      // 98304 -> 2 CTAs/SM

// ---------------- static device scratch ----------------
__device__ float g_xr  [(size_t)MTOK * HDIM];
__device__ float g_sguwr[(size_t)(2 * SHI) * HDIM];
__device__ float g_sdwr[(size_t)HDIM * SHI];
__device__ float g_w13r[(size_t)NEXP * (2 * MOEI) * HDIM];
__device__ float g_w2r [(size_t)NEXP * HDIM * MOEI];
__device__ float g_actS[(size_t)MTOK * SHI];
__device__ float g_eact[(size_t)NEXP * CAP * MOEI];
__device__ float g_moe [(size_t)NEXP * CAP * HDIM];
__device__ float g_gateS[MTOK];
__device__ int   g_counts[NEXP];
__device__ int   g_perm [NEXP * CAP];
__device__ int   g_slot [MTOK * 2];
__device__ float g_wt   [MTOK * 2];

// ---------------- PTX helpers ----------------
__device__ __forceinline__ uint32_t smem_u32(const void* p) {
    uint32_t a;
    asm("{ .reg .u64 t; cvta.to.shared.u64 t, %1; cvt.u32.u64 %0, t; }" : "=r"(a) : "l"(p));
    return a;
}
#define CP16(dst, src) \
    asm volatile("cp.async.cg.shared.global [%0], [%1], 16;" :: "r"(dst), "l"(src))
#define CP_COMMIT() asm volatile("cp.async.commit_group;" ::: "memory")
#define CP_WAIT(n)  asm volatile("cp.async.wait_group %0;" :: "n"(n) : "memory")

#define LDSM4(r0, r1, r2, r3, addr) \
    asm volatile("ldmatrix.sync.aligned.m8n8.x4.shared.b16 {%0,%1,%2,%3}, [%4];" \
        : "=r"(r0), "=r"(r1), "=r"(r2), "=r"(r3) : "r"(addr))

__device__ __forceinline__ uint32_t to_tf32(float f) {
    uint32_t r;
    asm("cvt.rna.tf32.f32 %0, %1;" : "=r"(r) : "f"(f));
    return r;
}
__device__ __forceinline__ void mma_tf32(float* c, const uint32_t* a, const uint32_t* b) {
    asm volatile(
        "mma.sync.aligned.m16n8k8.row.col.f32.tf32.tf32.f32 "
        "{%0,%1,%2,%3}, {%4,%5,%6,%7}, {%8,%9}, {%0,%1,%2,%3};"
        : "+f"(c[0]), "+f"(c[1]), "+f"(c[2]), "+f"(c[3])
        : "r"(a[0]), "r"(a[1]), "r"(a[2]), "r"(a[3]), "r"(b[0]), "r"(b[1]));
}

// ---------------- elementwise tf32 pre-round ----------------
__global__ void round_kernel(const float* __restrict__ in, float* __restrict__ out, long n4)
{
    long i = (long)blockIdx.x * blockDim.x + threadIdx.x;
    if (i >= n4) return;
    float4 v = ((const float4*)in)[i];
    uint4 r;
    r.x = to_tf32(v.x); r.y = to_tf32(v.y); r.z = to_tf32(v.z); r.w = to_tf32(v.w);
    ((uint4*)out)[i] = r;
}

// ---------------- small kernels ----------------
__global__ void init_kernel() {
    if (threadIdx.x < NEXP) g_counts[threadIdx.x] = 0;
}

__global__ void router_kernel(const float* __restrict__ x,
                              const float* __restrict__ gate_w,
                              const float* __restrict__ shared_gate_w)
{
    int m = blockIdx.x, tid = threadIdx.x, w = tid >> 5, lane = tid & 31;
    const float* xr = x + (size_t)m * HDIM;
    __shared__ float s_log[NEXP];
    __shared__ float s_sg;
    {
        const float* gw = gate_w + (size_t)w * HDIM;
        float sum = 0.f;
        for (int k = lane; k < HDIM; k += 32) sum += xr[k] * gw[k];
        #pragma unroll
        for (int o = 16; o; o >>= 1) sum += __shfl_xor_sync(0xffffffffu, sum, o);
        if (lane == 0) s_log[w] = sum;
    }
    if (w == 0) {
        float sg = 0.f;
        for (int k = lane; k < HDIM; k += 32) sg += xr[k] * shared_gate_w[k];
        #pragma unroll
        for (int o = 16; o; o >>= 1) sg += __shfl_xor_sync(0xffffffffu, sg, o);
        if (lane == 0) s_sg = sg;
    }
    __syncthreads();
    if (tid == 0) {
        float mx = -1e30f;
        #pragma unroll
        for (int e = 0; e < NEXP; e++) mx = fmaxf(mx, s_log[e]);
        float p[NEXP]; float den = 0.f;
        #pragma unroll
        for (int e = 0; e < NEXP; e++) { p[e] = expf(s_log[e] - mx); den += p[e]; }
        float inv = 1.f / den;
        int i1 = 0; float p1 = -1.f;
        #pragma unroll
        for (int e = 0; e < NEXP; e++) if (p[e] > p1) { p1 = p[e]; i1 = e; }
        int i2 = -1; float p2 = -1.f;
        #pragma unroll
        for (int e = 0; e < NEXP; e++) { if (e == i1) continue; if (p[e] > p2) { p2 = p[e]; i2 = e; } }
        p1 *= inv; p2 *= inv;
        g_gateS[m] = 1.f / (1.f + expf(-s_sg));
        int pos1 = atomicAdd(&g_counts[i1], 1);
        g_perm[i1 * CAP + pos1] = m;
        g_slot[2 * m + 0] = i1 * CAP + pos1;
        g_wt  [2 * m + 0] = p1;
        int pos2 = atomicAdd(&g_counts[i2], 1);
        g_perm[i2 * CAP + pos2] = m;
        g_slot[2 * m + 1] = i2 * CAP + pos2;
        g_wt  [2 * m + 1] = p2;
    }
}

__global__ void combine_kernel(float* __restrict__ out)
{
    int m  = blockIdx.y;
    int c4 = blockIdx.x * blockDim.x + threadIdx.x;
    if (c4 >= (HDIM >> 2)) return;
    int ci = c4 << 2;
    int   s0 = g_slot[2 * m + 0], s1 = g_slot[2 * m + 1];
    float w0 = g_wt  [2 * m + 0], w1 = g_wt  [2 * m + 1];
    float4 h0 = *(const float4*)(g_moe + (size_t)s0 * HDIM + ci);
    float4 h1 = *(const float4*)(g_moe + (size_t)s1 * HDIM + ci);
    float4 o  = *(float4*)(out + (size_t)m * HDIM + ci);
    o.x += w0 * h0.x + w1 * h1.x;
    o.y += w0 * h0.y + w1 * h1.y;
    o.z += w0 * h0.z + w1 * h1.z;
    o.w += w0 * h0.w + w1 * h1.w;
    *(float4*)(out + (size_t)m * HDIM + ci) = o;
}

// ---------------- tf32 mma.sync GEMM (ldmatrix fragments, pre-rounded operands) ----------------
// MODE 0: act = silu(A·Wg^T) * (A·Wu^T), output tile 128x64, tf32-rounded store.
// MODE 1: C = (A·W^T) * rowScale, output tile 128x128.
template<int MODE>
__global__ __launch_bounds__(256, 2)
void mma_gemm(const float* __restrict__ Abase, const float* __restrict__ Wbase,
              float* __restrict__ Cbase, int I, int K,
              long sA, long sW, long sC,
              const int* __restrict__ counts, int Mfull,
              const int* __restrict__ perm, const float* __restrict__ rowScale)
{
    int e = blockIdx.z;
    int cnt = counts ? counts[e] : Mfull;
    int m0 = blockIdx.y * BM;
    if (m0 >= cnt) return;

    const float* A = Abase + (long)e * sA;
    const float* W = Wbase + (long)e * sW;
    float* C = Cbase + (long)e * sC;
    const int* pm = perm ? perm + e * CAP : (const int*)0;

    extern __shared__ float smem[];
    uint32_t smem_b = smem_u32(smem);

    int tid = threadIdx.x;
    int lane = tid & 31, wid = tid >> 5;
    int warpM = wid & 3, warpN = wid >> 2;

    // ---- producer mapping: thread t fills row lr, k-half kh (16 floats via 4x CP16) ----
    int lr = tid >> 1;
    int kh = (tid & 1) * 16;
    int gr = m0 + lr;
    long arow = pm ? (long)((gr < cnt) ? pm[gr] : 0) : (long)((gr < cnt) ? gr : 0);
    const float* aptr = A + arow * (long)K + kh;
    long wrow;
    int n0g = 0;
    if (MODE == 0) {
        n0g = blockIdx.x * 64;
        wrow = (lr < 64) ? (long)(n0g + lr) : (long)(I + n0g + (lr - 64));
    } else {
        wrow = (long)(blockIdx.x * BN + lr);
    }
    const float* bptr = W + wrow * (long)K + kh;
    uint32_t xb = (uint32_t)(lr & 7) << 4;                 // write swizzle (bytes)
    uint32_t arow_b = smem_b + (uint32_t)lr * 128u;
    uint32_t brow_b = arow_b + 128u * 128u;
    uint32_t kb = (uint32_t)kh * 4u;

    // ---- ldmatrix per-lane address components ----
    // A, per mt: matrix mi = lane>>3 ; row = warpM*32 + mt*16 + (mi&1)*8 + (lane&7)
    //            chunk offset = (mi>>1)*16 bytes beyond kc-chunk
    int li = lane & 7, mi = lane >> 3;
    uint32_t a_off[2], a_xor[2];
    #pragma unroll
    for (int mt = 0; mt < 2; mt++) {
        int row = warpM * 32 + mt * 16 + (mi & 1) * 8 + li;
        a_off[mt] = (uint32_t)row * 128u;
        a_xor[mt] = (uint32_t)(row & 7) << 4;
    }
    uint32_t a_ck = (uint32_t)(mi >> 1) << 4;
    // B, per group g (covers nt=2g, 2g+1): n = warpN*64 + (2g + (mi>>1))*8 + li
    //            chunk offset = (mi&1)*16
    uint32_t b_off[4], b_xor[4];
    #pragma unroll
    for (int g = 0; g < 4; g++) {
        int n = warpN * 64 + (2 * g + (mi >> 1)) * 8 + li;
        b_off[g] = (uint32_t)n * 128u;
        b_xor[g] = (uint32_t)(n & 7) << 4;
    }
    uint32_t b_ck = (uint32_t)(mi & 1) << 4;

    int KI = K / BK;

    // prologue: stages 0..NSTAGE-2
    #pragma unroll
    for (int s = 0; s < NSTAGE - 1; s++) {
        const float* a = aptr + s * BK;
        const float* b = bptr + s * BK;
        uint32_t so = (uint32_t)s * STAGE_BYTES;
        #pragma unroll
        for (int j = 0; j < 4; j++) CP16(arow_b + so + ((kb + j * 16) ^ xb), a + j * 4);
        #pragma unroll
        for (int j = 0; j < 4; j++) CP16(brow_b + so + ((kb + j * 16) ^ xb), b + j * 4);
        CP_COMMIT();
    }

    float acc[2][8][4];
    #pragma unroll
    for (int i = 0; i < 2; i++)
        #pragma unroll
        for (int j = 0; j < 8; j++)
            #pragma unroll
            for (int q = 0; q < 4; q++) acc[i][j][q] = 0.f;

    #pragma unroll 1
    for (int k = 0; k < KI; k++) {
        if (k <= KI - NSTAGE) { CP_WAIT(NSTAGE - 2); } else { CP_WAIT(0); }
        __syncthreads();

        int kn = k + NSTAGE - 1;
        if (kn < KI) {
            const float* a = aptr + kn * BK;
            const float* b = bptr + kn * BK;
            uint32_t so = (uint32_t)(kn % NSTAGE) * STAGE_BYTES;
            #pragma unroll
            for (int j = 0; j < 4; j++) CP16(arow_b + so + ((kb + j * 16) ^ xb), a + j * 4);
            #pragma unroll
            for (int j = 0; j < 4; j++) CP16(brow_b + so + ((kb + j * 16) ^ xb), b + j * 4);
            CP_COMMIT();
        }

        uint32_t stA = smem_b + (uint32_t)(k % NSTAGE) * STAGE_BYTES;
        uint32_t stB = stA + 128u * 128u;

        #pragma unroll
        for (int kc = 0; kc < BK; kc += 8) {
            uint32_t kcb = (uint32_t)kc * 4u;              // kc-chunk byte base
            uint32_t af[2][4], bf[8][2];
            #pragma unroll
            for (int mt = 0; mt < 2; mt++) {
                uint32_t ad = stA + a_off[mt] + ((kcb + a_ck) ^ a_xor[mt]);
                LDSM4(af[mt][0], af[mt][1], af[mt][2], af[mt][3], ad);
            }
            #pragma unroll
            for (int g = 0; g < 4; g++) {
                uint32_t bd = stB + b_off[g] + ((kcb + b_ck) ^ b_xor[g]);
                LDSM4(bf[2 * g][0], bf[2 * g][1], bf[2 * g + 1][0], bf[2 * g + 1][1], bd);
            }
            #pragma unroll
            for (int mt = 0; mt < 2; mt++)
                #pragma unroll
                for (int nt = 0; nt < 8; nt++)
                    mma_tf32(acc[mt][nt], af[mt], bf[nt]);
        }
    }

    int r = lane >> 2;
    if (MODE == 1) {
        int n0 = blockIdx.x * BN;
        int c2 = (lane & 3) * 2;
        #pragma unroll
        for (int mt = 0; mt < 2; mt++) {
            #pragma unroll
            for (int half = 0; half < 2; half++) {
                int row = m0 + warpM * 32 + mt * 16 + half * 8 + r;
                if (row >= cnt) continue;
                float sc = rowScale ? rowScale[row] : 1.f;
                float* crow = C + (long)row * I + n0 + warpN * 64;
                #pragma unroll
                for (int nt = 0; nt < 8; nt++) {
                    float2 v;
                    v.x = acc[mt][nt][half * 2 + 0] * sc;
                    v.y = acc[mt][nt][half * 2 + 1] * sc;
                    *(float2*)(crow + nt * 8 + c2) = v;
                }
            }
        }
    } else {
        // stage accumulators through smem to pair gate/up columns (cp.async fully drained)
        __syncthreads();
        float* Cs = smem;               // [128][132]
        int c2 = (lane & 3) * 2;
        #pragma unroll
        for (int mt = 0; mt < 2; mt++)
            #pragma unroll
            for (int half = 0; half < 2; half++) {
                int rr = warpM * 32 + mt * 16 + half * 8 + r;
                #pragma unroll
                for (int nt = 0; nt < 8; nt++) {
                    float2 v;
                    v.x = acc[mt][nt][half * 2 + 0];
                    v.y = acc[mt][nt][half * 2 + 1];
                    *(float2*)(Cs + rr * 132 + warpN * 64 + nt * 8 + c2) = v;
                }
            }
        __syncthreads();
        int row = tid >> 1;
        int cb = (tid & 1) * 32;
        if (m0 + row < cnt) {
            float* crow = C + (long)(m0 + row) * I + n0g;
            #pragma unroll
            for (int j = 0; j < 32; j += 4) {
                float4 g = *(const float4*)(Cs + row * 132 + cb + j);
                float4 u = *(const float4*)(Cs + row * 132 + 64 + cb + j);
                uint4 o;
                o.x = to_tf32(g.x / (1.f + __expf(-g.x)) * u.x);
                o.y = to_tf32(g.y / (1.f + __expf(-g.y)) * u.y);
                o.z = to_tf32(g.z / (1.f + __expf(-g.z)) * u.z);
                o.w = to_tf32(g.w / (1.f + __expf(-g.w)) * u.w);
                *(uint4*)(crow + cb + j) = o;
            }
        }
    }
}

// ---------------- launch ----------------
static inline void round_launch(const float* in, float* out, long n) {
    long n4 = n >> 2;
    round_kernel<<<(unsigned)((n4 + 255) / 256), 256>>>(in, out, n4);
}

extern "C" void kernel_launch(void* const* d_in, const int* in_sizes, int n_in,
                              void* d_out, int out_size)
{
    (void)in_sizes; (void)n_in; (void)out_size;
    const float* x    = (const float*)d_in[0];
    const float* gw   = (const float*)d_in[1];
    const float* sgw  = (const float*)d_in[2];
    const float* sguw = (const float*)d_in[3];
    const float* sdw  = (const float*)d_in[4];
    const float* w13  = (const float*)d_in[5];
    const float* w2   = (const float*)d_in[6];
    float* out = (float*)d_out;

    float *xr, *sguwr, *sdwr, *w13r, *w2r, *actS, *eact, *moe, *gateS;
    int *counts, *perm;
    cudaGetSymbolAddress((void**)&xr,     g_xr);
    cudaGetSymbolAddress((void**)&sguwr,  g_sguwr);
    cudaGetSymbolAddress((void**)&sdwr,   g_sdwr);
    cudaGetSymbolAddress((void**)&w13r,   g_w13r);
    cudaGetSymbolAddress((void**)&w2r,    g_w2r);
    cudaGetSymbolAddress((void**)&actS,   g_actS);
    cudaGetSymbolAddress((void**)&eact,   g_eact);
    cudaGetSymbolAddress((void**)&moe,    g_moe);
    cudaGetSymbolAddress((void**)&gateS,  g_gateS);
    cudaGetSymbolAddress((void**)&counts, g_counts);
    cudaGetSymbolAddress((void**)&perm,   g_perm);

    cudaFuncSetAttribute(mma_gemm<0>, cudaFuncAttributeMaxDynamicSharedMemorySize, SMEM_TOTAL);
    cudaFuncSetAttribute(mma_gemm<1>, cudaFuncAttributeMaxDynamicSharedMemorySize, SMEM_TOTAL);

    init_kernel<<<1, 32>>>();
    router_kernel<<<MTOK, 256>>>(x, gw, sgw);

    // pre-round operands to tf32 (rna) once
    round_launch(x,    xr,    (long)MTOK * HDIM);
    round_launch(sguw, sguwr, (long)(2 * SHI) * HDIM);
    round_launch(sdw,  sdwr,  (long)HDIM * SHI);
    round_launch(w13,  w13r,  (long)NEXP * (2 * MOEI) * HDIM);
    round_launch(w2,   w2r,   (long)NEXP * HDIM * MOEI);

    // shared expert gate_up (fused silu*mul, tf32-rounded output)
    mma_gemm<0><<<dim3(SHI / 64, MTOK / BM, 1), 256, SMEM_TOTAL>>>(
        xr, sguwr, actS, SHI, HDIM, 0, 0, 0, nullptr, MTOK, nullptr, nullptr);
    // routed experts gate_up (gathered, fused silu*mul)
    mma_gemm<0><<<dim3(MOEI / 64, CAP / BM, NEXP), 256, SMEM_TOTAL>>>(
        xr, w13r, eact, MOEI, HDIM,
        0, (long)(2 * MOEI) * HDIM, (long)CAP * MOEI,
        counts, CAP, perm, nullptr);
    // shared down (fused sigmoid token gate) -> out
    mma_gemm<1><<<dim3(HDIM / BN, MTOK / BM, 1), 256, SMEM_TOTAL>>>(
        actS, sdwr, out, HDIM, SHI, 0, 0, 0, nullptr, MTOK, nullptr, gateS);
    // expert down
    mma_gemm<1><<<dim3(HDIM / BN, CAP / BM, NEXP), 256, SMEM_TOTAL>>>(
        eact, w2r, moe, HDIM, MOEI,
        (long)CAP * MOEI, (long)HDIM * MOEI, (long)CAP * HDIM,
        counts, CAP, nullptr, nullptr);

    combine_kernel<<<dim3((HDIM / 4 + 255) / 256, MTOK, 1), 256>>>(out);
}

// round 9
// speedup vs baseline: 1.0403x; 1.0403x over previous
#include <cuda_runtime.h>
#include <cstdint>
#include <math.h>

#define MTOK 4096
#define HDIM 2048
#define NEXP 8
#define MOEI 1408
#define SHI  5632
#define CAP  4096

#define BM 128
#define BN 128
#define BK 32
#define NSTAGE 3
#define STAGE_FLOATS (2 * 128 * 32)              // A tile + B tile, swizzled
#define STAGE_BYTES  (STAGE_FLOATS * 4)          // 32768
#define SMEM_TOTAL   (NSTAGE * STAGE_BYTES)      // 98304 -> 2 CTAs/SM

// ---------------- static device scratch ----------------
__device__ float g_xr  [(size_t)MTOK * HDIM];
__device__ float g_sguwr[(size_t)(2 * SHI) * HDIM];
__device__ float g_sdwr[(size_t)HDIM * SHI];
__device__ float g_w13r[(size_t)NEXP * (2 * MOEI) * HDIM];
__device__ float g_w2r [(size_t)NEXP * HDIM * MOEI];
__device__ float g_actS[(size_t)MTOK * SHI];
__device__ float g_eact[(size_t)NEXP * CAP * MOEI];
__device__ float g_moe [(size_t)NEXP * CAP * HDIM];
__device__ float g_gateS[MTOK];
__device__ int   g_counts[NEXP];
__device__ int   g_perm [NEXP * CAP];
__device__ int   g_slot [MTOK * 2];
__device__ float g_wt   [MTOK * 2];

// ---------------- PTX helpers ----------------
__device__ __forceinline__ uint32_t smem_u32(const void* p) {
    uint32_t a;
    asm("{ .reg .u64 t; cvta.to.shared.u64 t, %1; cvt.u32.u64 %0, t; }" : "=r"(a) : "l"(p));
    return a;
}
#define CP16(dst, src) \
    asm volatile("cp.async.cg.shared.global [%0], [%1], 16;" :: "r"(dst), "l"(src))
#define CP_COMMIT() asm volatile("cp.async.commit_group;" ::: "memory")
#define CP_WAIT(n)  asm volatile("cp.async.wait_group %0;" :: "n"(n) : "memory")

__device__ __forceinline__ uint32_t to_tf32(float f) {
    uint32_t r;
    asm("cvt.rna.tf32.f32 %0, %1;" : "=r"(r) : "f"(f));
    return r;
}
__device__ __forceinline__ void mma_tf32(float* c, const uint32_t* a, const uint32_t* b) {
    asm volatile(
        "mma.sync.aligned.m16n8k8.row.col.f32.tf32.tf32.f32 "
        "{%0,%1,%2,%3}, {%4,%5,%6,%7}, {%8,%9}, {%0,%1,%2,%3};"
        : "+f"(c[0]), "+f"(c[1]), "+f"(c[2]), "+f"(c[3])
        : "r"(a[0]), "r"(a[1]), "r"(a[2]), "r"(a[3]), "r"(b[0]), "r"(b[1]));
}

// ---------------- elementwise tf32 pre-round ----------------
__global__ void round_kernel(const float* __restrict__ in, float* __restrict__ out, long n4)
{
    long i = (long)blockIdx.x * blockDim.x + threadIdx.x;
    if (i >= n4) return;
    float4 v = ((const float4*)in)[i];
    uint4 r;
    r.x = to_tf32(v.x); r.y = to_tf32(v.y); r.z = to_tf32(v.z); r.w = to_tf32(v.w);
    ((uint4*)out)[i] = r;
}

// ---------------- small kernels ----------------
__global__ void init_kernel() {
    if (threadIdx.x < NEXP) g_counts[threadIdx.x] = 0;
}

__global__ void router_kernel(const float* __restrict__ x,
                              const float* __restrict__ gate_w,
                              const float* __restrict__ shared_gate_w)
{
    int m = blockIdx.x, tid = threadIdx.x, w = tid >> 5, lane = tid & 31;
    const float* xr = x + (size_t)m * HDIM;
    __shared__ float s_log[NEXP];
    __shared__ float s_sg;
    {
        const float* gw = gate_w + (size_t)w * HDIM;
        float sum = 0.f;
        for (int k = lane; k < HDIM; k += 32) sum += xr[k] * gw[k];
        #pragma unroll
        for (int o = 16; o; o >>= 1) sum += __shfl_xor_sync(0xffffffffu, sum, o);
        if (lane == 0) s_log[w] = sum;
    }
    if (w == 0) {
        float sg = 0.f;
        for (int k = lane; k < HDIM; k += 32) sg += xr[k] * shared_gate_w[k];
        #pragma unroll
        for (int o = 16; o; o >>= 1) sg += __shfl_xor_sync(0xffffffffu, sg, o);
        if (lane == 0) s_sg = sg;
    }
    __syncthreads();
    if (tid == 0) {
        float mx = -1e30f;
        #pragma unroll
        for (int e = 0; e < NEXP; e++) mx = fmaxf(mx, s_log[e]);
        float p[NEXP]; float den = 0.f;
        #pragma unroll
        for (int e = 0; e < NEXP; e++) { p[e] = expf(s_log[e] - mx); den += p[e]; }
        float inv = 1.f / den;
        int i1 = 0; float p1 = -1.f;
        #pragma unroll
        for (int e = 0; e < NEXP; e++) if (p[e] > p1) { p1 = p[e]; i1 = e; }
        int i2 = -1; float p2 = -1.f;
        #pragma unroll
        for (int e = 0; e < NEXP; e++) { if (e == i1) continue; if (p[e] > p2) { p2 = p[e]; i2 = e; } }
        p1 *= inv; p2 *= inv;
        g_gateS[m] = 1.f / (1.f + expf(-s_sg));
        int pos1 = atomicAdd(&g_counts[i1], 1);
        g_perm[i1 * CAP + pos1] = m;
        g_slot[2 * m + 0] = i1 * CAP + pos1;
        g_wt  [2 * m + 0] = p1;
        int pos2 = atomicAdd(&g_counts[i2], 1);
        g_perm[i2 * CAP + pos2] = m;
        g_slot[2 * m + 1] = i2 * CAP + pos2;
        g_wt  [2 * m + 1] = p2;
    }
}

__global__ void combine_kernel(float* __restrict__ out)
{
    int m  = blockIdx.y;
    int c4 = blockIdx.x * blockDim.x + threadIdx.x;
    if (c4 >= (HDIM >> 2)) return;
    int ci = c4 << 2;
    int   s0 = g_slot[2 * m + 0], s1 = g_slot[2 * m + 1];
    float w0 = g_wt  [2 * m + 0], w1 = g_wt  [2 * m + 1];
    float4 h0 = *(const float4*)(g_moe + (size_t)s0 * HDIM + ci);
    float4 h1 = *(const float4*)(g_moe + (size_t)s1 * HDIM + ci);
    float4 o  = *(float4*)(out + (size_t)m * HDIM + ci);
    o.x += w0 * h0.x + w1 * h1.x;
    o.y += w0 * h0.y + w1 * h1.y;
    o.z += w0 * h0.z + w1 * h1.z;
    o.w += w0 * h0.w + w1 * h1.w;
    *(float4*)(out + (size_t)m * HDIM + ci) = o;
}

// ---------------- tf32 mma.sync GEMM: 128 threads, 4 warps (2Mx2N), warp tile 64x64 ----------------
// MODE 0: act = silu(A·Wg^T) * (A·Wu^T), output tile 128x64, tf32-rounded store.
// MODE 1: C = (A·W^T) * rowScale, output tile 128x128.
template<int MODE>
__global__ __launch_bounds__(128, 2)
void mma_gemm(const float* __restrict__ Abase, const float* __restrict__ Wbase,
              float* __restrict__ Cbase, int I, int K,
              long sA, long sW, long sC,
              const int* __restrict__ counts, int Mfull,
              const int* __restrict__ perm, const float* __restrict__ rowScale)
{
    int e = blockIdx.z;
    int cnt = counts ? counts[e] : Mfull;
    int m0 = blockIdx.y * BM;
    if (m0 >= cnt) return;

    const float* A = Abase + (long)e * sA;
    const float* W = Wbase + (long)e * sW;
    float* C = Cbase + (long)e * sC;
    const int* pm = perm ? perm + e * CAP : (const int*)0;

    extern __shared__ float smem[];
    uint32_t smem_b = smem_u32(smem);

    int tid = threadIdx.x;
    int lane = tid & 31, wid = tid >> 5;
    int warpM = wid & 1, warpN = wid >> 1;

    // ---- producer mapping: thread t fills full row lr of A and B (8x CP16 each) ----
    int lr = tid;
    int gr = m0 + lr;
    long arow = pm ? (long)((gr < cnt) ? pm[gr] : 0) : (long)((gr < cnt) ? gr : 0);
    const float* aptr = A + arow * (long)K;
    long wrow;
    int n0g = 0;
    if (MODE == 0) {
        n0g = blockIdx.x * 64;
        wrow = (lr < 64) ? (long)(n0g + lr) : (long)(I + n0g + (lr - 64));
    } else {
        wrow = (long)(blockIdx.x * BN + lr);
    }
    const float* bptr = W + wrow * (long)K;
    uint32_t xb = (uint32_t)(lr & 7) << 4;                 // write swizzle (bytes)
    uint32_t arow_b = smem_b + (uint32_t)lr * 128u;
    uint32_t brow_b = arow_b + 128u * 128u;

    int KI = K / BK;

    // prologue: stages 0..NSTAGE-2
    #pragma unroll
    for (int s = 0; s < NSTAGE - 1; s++) {
        const float* a = aptr + s * BK;
        const float* b = bptr + s * BK;
        uint32_t so = (uint32_t)s * STAGE_BYTES;
        #pragma unroll
        for (int j = 0; j < 8; j++) CP16(arow_b + so + ((j * 16) ^ xb), a + j * 4);
        #pragma unroll
        for (int j = 0; j < 8; j++) CP16(brow_b + so + ((j * 16) ^ xb), b + j * 4);
        CP_COMMIT();
    }

    float acc[4][8][4];
    #pragma unroll
    for (int i = 0; i < 4; i++)
        #pragma unroll
        for (int j = 0; j < 8; j++)
            #pragma unroll
            for (int q = 0; q < 4; q++) acc[i][j][q] = 0.f;

    int r = lane >> 2, cq = lane & 3;
    int xw = r << 2;                                       // read swizzle (floats)

    #pragma unroll 1
    for (int k = 0; k < KI; k++) {
        if (k <= KI - NSTAGE) { CP_WAIT(NSTAGE - 2); } else { CP_WAIT(0); }
        __syncthreads();

        int kn = k + NSTAGE - 1;
        if (kn < KI) {
            const float* a = aptr + kn * BK;
            const float* b = bptr + kn * BK;
            uint32_t so = (uint32_t)(kn % NSTAGE) * STAGE_BYTES;
            #pragma unroll
            for (int j = 0; j < 8; j++) CP16(arow_b + so + ((j * 16) ^ xb), a + j * 4);
            #pragma unroll
            for (int j = 0; j < 8; j++) CP16(brow_b + so + ((j * 16) ^ xb), b + j * 4);
            CP_COMMIT();
        }

        const uint32_t* As = (const uint32_t*)(smem + (k % NSTAGE) * STAGE_FLOATS);
        const uint32_t* Bs = As + 128 * 32;

        #pragma unroll
        for (int kc = 0; kc < BK; kc += 8) {
            int cl = (kc + cq) ^ xw;
            int ch = (kc + 4 + cq) ^ xw;
            uint32_t af[4][4], bf[8][2];
            #pragma unroll
            for (int mt = 0; mt < 4; mt++) {
                int mb = warpM * 64 + mt * 16;
                af[mt][0] = As[(mb + r)     * 32 + cl];
                af[mt][1] = As[(mb + 8 + r) * 32 + cl];
                af[mt][2] = As[(mb + r)     * 32 + ch];
                af[mt][3] = As[(mb + 8 + r) * 32 + ch];
            }
            #pragma unroll
            for (int nt = 0; nt < 8; nt++) {
                int nb = warpN * 64 + nt * 8;
                bf[nt][0] = Bs[(nb + r) * 32 + cl];
                bf[nt][1] = Bs[(nb + r) * 32 + ch];
            }
            #pragma unroll
            for (int mt = 0; mt < 4; mt++)
                #pragma unroll
                for (int nt = 0; nt < 8; nt++)
                    mma_tf32(acc[mt][nt], af[mt], bf[nt]);
        }
    }

    if (MODE == 1) {
        int n0 = blockIdx.x * BN;
        int c2 = (lane & 3) * 2;
        #pragma unroll
        for (int mt = 0; mt < 4; mt++) {
            #pragma unroll
            for (int half = 0; half < 2; half++) {
                int row = m0 + warpM * 64 + mt * 16 + half * 8 + r;
                if (row >= cnt) continue;
                float sc = rowScale ? rowScale[row] : 1.f;
                float* crow = C + (long)row * I + n0 + warpN * 64;
                #pragma unroll
                for (int nt = 0; nt < 8; nt++) {
                    float2 v;
                    v.x = acc[mt][nt][half * 2 + 0] * sc;
                    v.y = acc[mt][nt][half * 2 + 1] * sc;
                    *(float2*)(crow + nt * 8 + c2) = v;
                }
            }
        }
    } else {
        // stage accumulators through smem to pair gate/up columns (cp.async fully drained)
        __syncthreads();
        float* Cs = smem;               // [128][132]
        int c2 = (lane & 3) * 2;
        #pragma unroll
        for (int mt = 0; mt < 4; mt++)
            #pragma unroll
            for (int half = 0; half < 2; half++) {
                int rr = warpM * 64 + mt * 16 + half * 8 + r;
                #pragma unroll
                for (int nt = 0; nt < 8; nt++) {
                    float2 v;
                    v.x = acc[mt][nt][half * 2 + 0];
                    v.y = acc[mt][nt][half * 2 + 1];
                    *(float2*)(Cs + rr * 132 + warpN * 64 + nt * 8 + c2) = v;
                }
            }
        __syncthreads();
        int row = tid;
        if (m0 + row < cnt) {
            float* crow = C + (long)(m0 + row) * I + n0g;
            #pragma unroll
            for (int j = 0; j < 64; j += 4) {
                float4 g = *(const float4*)(Cs + row * 132 + j);
                float4 u = *(const float4*)(Cs + row * 132 + 64 + j);
                uint4 o;
                o.x = to_tf32(g.x / (1.f + __expf(-g.x)) * u.x);
                o.y = to_tf32(g.y / (1.f + __expf(-g.y)) * u.y);
                o.z = to_tf32(g.z / (1.f + __expf(-g.z)) * u.z);
                o.w = to_tf32(g.w / (1.f + __expf(-g.w)) * u.w);
                *(uint4*)(crow + j) = o;
            }
        }
    }
}

// ---------------- launch ----------------
static inline void round_launch(const float* in, float* out, long n) {
    long n4 = n >> 2;
    round_kernel<<<(unsigned)((n4 + 255) / 256), 256>>>(in, out, n4);
}

extern "C" void kernel_launch(void* const* d_in, const int* in_sizes, int n_in,
                              void* d_out, int out_size)
{
    (void)in_sizes; (void)n_in; (void)out_size;
    const float* x    = (const float*)d_in[0];
    const float* gw   = (const float*)d_in[1];
    const float* sgw  = (const float*)d_in[2];
    const float* sguw = (const float*)d_in[3];
    const float* sdw  = (const float*)d_in[4];
    const float* w13  = (const float*)d_in[5];
    const float* w2   = (const float*)d_in[6];
    float* out = (float*)d_out;

    float *xr, *sguwr, *sdwr, *w13r, *w2r, *actS, *eact, *moe, *gateS;
    int *counts, *perm;
    cudaGetSymbolAddress((void**)&xr,     g_xr);
    cudaGetSymbolAddress((void**)&sguwr,  g_sguwr);
    cudaGetSymbolAddress((void**)&sdwr,   g_sdwr);
    cudaGetSymbolAddress((void**)&w13r,   g_w13r);
    cudaGetSymbolAddress((void**)&w2r,    g_w2r);
    cudaGetSymbolAddress((void**)&actS,   g_actS);
    cudaGetSymbolAddress((void**)&eact,   g_eact);
    cudaGetSymbolAddress((void**)&moe,    g_moe);
    cudaGetSymbolAddress((void**)&gateS,  g_gateS);
    cudaGetSymbolAddress((void**)&counts, g_counts);
    cudaGetSymbolAddress((void**)&perm,   g_perm);

    cudaFuncSetAttribute(mma_gemm<0>, cudaFuncAttributeMaxDynamicSharedMemorySize, SMEM_TOTAL);
    cudaFuncSetAttribute(mma_gemm<1>, cudaFuncAttributeMaxDynamicSharedMemorySize, SMEM_TOTAL);

    init_kernel<<<1, 32>>>();
    router_kernel<<<MTOK, 256>>>(x, gw, sgw);

    // pre-round operands to tf32 (rna) once
    round_launch(x,    xr,    (long)MTOK * HDIM);
    round_launch(sguw, sguwr, (long)(2 * SHI) * HDIM);
    round_launch(sdw,  sdwr,  (long)HDIM * SHI);
    round_launch(w13,  w13r,  (long)NEXP * (2 * MOEI) * HDIM);
    round_launch(w2,   w2r,   (long)NEXP * HDIM * MOEI);

    // shared expert gate_up (fused silu*mul, tf32-rounded output)
    mma_gemm<0><<<dim3(SHI / 64, MTOK / BM, 1), 128, SMEM_TOTAL>>>(
        xr, sguwr, actS, SHI, HDIM, 0, 0, 0, nullptr, MTOK, nullptr, nullptr);
    // routed experts gate_up (gathered, fused silu*mul)
    mma_gemm<0><<<dim3(MOEI / 64, CAP / BM, NEXP), 128, SMEM_TOTAL>>>(
        xr, w13r, eact, MOEI, HDIM,
        0, (long)(2 * MOEI) * HDIM, (long)CAP * MOEI,
        counts, CAP, perm, nullptr);
    // shared down (fused sigmoid token gate) -> out
    mma_gemm<1><<<dim3(HDIM / BN, MTOK / BM, 1), 128, SMEM_TOTAL>>>(
        actS, sdwr, out, HDIM, SHI, 0, 0, 0, nullptr, MTOK, nullptr, gateS);
    // expert down
    mma_gemm<1><<<dim3(HDIM / BN, CAP / BM, NEXP), 128, SMEM_TOTAL>>>(
        eact, w2r, moe, HDIM, MOEI,
        (long)CAP * MOEI, (long)HDIM * MOEI, (long)CAP * HDIM,
        counts, CAP, nullptr, nullptr);

    combine_kernel<<<dim3((HDIM / 4 + 255) / 256, MTOK, 1), 256>>>(out);
}